// round 15
// baseline (speedup 1.0000x reference)
#include <cuda_runtime.h>
#include <cuda_fp16.h>
#include <math.h>
#include <stdint.h>

#define BB 4
#define TT 2048
#define CC 1024
#define HH 16
#define DH 64
#define MROWS (BB*TT)
#define C3   (3*CC)

// scratch (no cudaMalloc allowed)
__device__ __half g_qkv[(size_t)MROWS * C3];   // [M, 3C] fp16
__device__ __half g_y[(size_t)MROWS * CC];     // [M, C]  fp16
__device__ __half g_xh[(size_t)MROWS * CC];    // x fp16 [M, C]
__device__ __half g_wat[(size_t)C3 * CC];      // W_attn^T fp16 [3C, C]
__device__ __half g_wpt[(size_t)CC * CC];      // W_proj^T fp16 [C, C]

__device__ __forceinline__ uint32_t smem_u32(const void* p) {
    return (uint32_t)__cvta_generic_to_shared(p);
}
__device__ __forceinline__ void cpasync16(uint32_t dst_smem, const void* src) {
    asm volatile("cp.async.cg.shared.global [%0], [%1], 16;"
                 :: "r"(dst_smem), "l"(src));
}
__device__ __forceinline__ void ldsm4(uint32_t& r0, uint32_t& r1,
                                      uint32_t& r2, uint32_t& r3, uint32_t addr) {
    asm volatile("ldmatrix.sync.aligned.m8n8.x4.shared.b16 {%0,%1,%2,%3}, [%4];"
                 : "=r"(r0), "=r"(r1), "=r"(r2), "=r"(r3) : "r"(addr));
}
__device__ __forceinline__ void ldsm4t(uint32_t& r0, uint32_t& r1,
                                       uint32_t& r2, uint32_t& r3, uint32_t addr) {
    asm volatile("ldmatrix.sync.aligned.m8n8.x4.trans.shared.b16 {%0,%1,%2,%3}, [%4];"
                 : "=r"(r0), "=r"(r1), "=r"(r2), "=r"(r3) : "r"(addr));
}
#define HMMA(d, a, b)                                                        \
    asm volatile(                                                            \
        "mma.sync.aligned.m16n8k16.row.col.f32.f16.f16.f32 "                 \
        "{%0,%1,%2,%3}, {%4,%5,%6,%7}, {%8,%9}, {%0,%1,%2,%3};"              \
        : "+f"(d[0]), "+f"(d[1]), "+f"(d[2]), "+f"(d[3])                     \
        : "r"(a[0]), "r"(a[1]), "r"(a[2]), "r"(a[3]), "r"(b[0]), "r"(b[1]))

__device__ __forceinline__ uint32_t packexp2(float x, float y) {
    __half2 h = h2exp2(__floats2half2_rn(x, y));
    return *reinterpret_cast<uint32_t*>(&h);
}

// ====================== merged prep kernel (grid.z = 3) ====================
// z=0: tf32->fp16 round of x   z=1: W_attn transpose   z=2: W_proj transpose
__global__ void prep_all(const float* __restrict__ x, __half* __restrict__ xh,
                         const float* __restrict__ Wa, __half* __restrict__ Wat,
                         const float* __restrict__ Wp, __half* __restrict__ Wpt) {
    const int z = blockIdx.z;
    const int tx = threadIdx.x, ty = threadIdx.y;
    const int tid = ty * 32 + tx;
    if (z == 0) {
        const int n4 = MROWS * CC / 4;
        const int nth = gridDim.x * gridDim.y * 256;
        int base = (blockIdx.y * gridDim.x + blockIdx.x) * 256 + tid;
        for (int i = base; i < n4; i += nth) {
            float4 v = reinterpret_cast<const float4*>(x)[i];
            __half2* d = reinterpret_cast<__half2*>(xh) + 2 * i;
            d[0] = __floats2half2_rn(v.x, v.y);
            d[1] = __floats2half2_rn(v.z, v.w);
        }
        return;
    }
    __shared__ float t[32][33];
    const int Nn = (z == 1) ? C3 : CC;
    if (z == 2 && blockIdx.x >= CC / 32) return;
    const float* W = (z == 1) ? Wa : Wp;
    __half* Wt = (z == 1) ? Wat : Wpt;
    int n0 = blockIdx.x * 32, k0 = blockIdx.y * 32;
    #pragma unroll
    for (int j = 0; j < 4; j++)
        t[ty + j * 8][tx] = W[(size_t)(k0 + ty + j * 8) * Nn + n0 + tx];
    __syncthreads();
    #pragma unroll
    for (int j = 0; j < 4; j++)
        Wt[(size_t)(n0 + ty + j * 8) * CC + k0 + tx] =
            __float2half(t[tx][ty + j * 8]);
}

// ---------------------------------------------------------------------------
// FP16 GEMM: C[M,N] = A[M,K] @ Bt[N,K]^T + bias[N]
// block 256 (8 warps 2x4), tile 128x128, BK=64, 3-stage cp.async ring.
// B fragments double-buffered across ks steps (overlap ldsm with HMMA).
// ---------------------------------------------------------------------------
#define HSTR 72
#define HA_HALFS (128 * HSTR)
#define HSTAGE_BYTES (2 * HA_HALFS * 2)
#define HGEMM_SMEM_BYTES (3 * HSTAGE_BYTES)

__global__ __launch_bounds__(256, 2) void hgemm(
    const __half* __restrict__ A, const __half* __restrict__ Bt,
    const float* __restrict__ bias, void* __restrict__ Cm,
    int Mn, int Nn, int Kn, int half_out)
{
    extern __shared__ __half smh[];

    const int tid  = threadIdx.x;
    const int lane = tid & 31;
    const int warp = tid >> 5;
    const int wr   = warp & 1;
    const int wc   = warp >> 1;
    const int row0 = blockIdx.y * 128;
    const int col0 = blockIdx.x * 128;
    const int lr = lane >> 2;
    const int lc = lane & 3;

    const uint32_t smbase = smem_u32(smh);

    const int lmr = lane & 7, lmj = lane >> 3;
    const int a_loff = ((lmj & 1) * 8 + lmr) * HSTR + (lmj >> 1) * 8;
    const int b_loff = ((lmj >> 1) * 8 + lmr) * HSTR + (lmj & 1) * 8;

    int rr[4], k8[4];
    #pragma unroll
    for (int i = 0; i < 4; i++) {
        int f = tid + i * 256;
        rr[i] = f >> 3;
        k8[i] = (f & 7) << 3;
    }

    auto issue_stage = [&](int st, int k0) {
        uint32_t abase = smbase + st * HSTAGE_BYTES;
        uint32_t bbase = abase + HA_HALFS * 2;
        #pragma unroll
        for (int i = 0; i < 4; i++)
            cpasync16(abase + rr[i] * 144 + k8[i] * 2,
                      &A[(size_t)(row0 + rr[i]) * Kn + k0 + k8[i]]);
        #pragma unroll
        for (int i = 0; i < 4; i++)
            cpasync16(bbase + rr[i] * 144 + k8[i] * 2,
                      &Bt[(size_t)(col0 + rr[i]) * Kn + k0 + k8[i]]);
        asm volatile("cp.async.commit_group;");
    };

    float acc[4][4][4];
    #pragma unroll
    for (int i = 0; i < 4; i++)
        #pragma unroll
        for (int j = 0; j < 4; j++)
            #pragma unroll
            for (int k = 0; k < 4; k++) acc[i][j][k] = 0.0f;

    const int niter = Kn / 64;
    issue_stage(0, 0);
    if (niter > 1) issue_stage(1, 64);

    for (int it = 0; it < niter; it++) {
        if (it + 1 < niter) asm volatile("cp.async.wait_group 1;");
        else                asm volatile("cp.async.wait_group 0;");
        __syncthreads();

        if (it + 2 < niter) issue_stage((it + 2) % 3, (it + 2) * 64);

        const int stage = it % 3;
        const uint32_t aBase = smbase + stage * HSTAGE_BYTES;
        const uint32_t bBase = aBase + HA_HALFS * 2;

        // B fragments double-buffered across ks iterations
        uint32_t bq[2][4][2];
        {
            uint32_t r0, r1, r2, r3;
            ldsm4(r0, r1, r2, r3, bBase + ((wc * 32) * HSTR + b_loff) * 2);
            bq[0][0][0] = r0; bq[0][0][1] = r1;
            bq[0][1][0] = r2; bq[0][1][1] = r3;
            ldsm4(r0, r1, r2, r3, bBase + ((wc * 32 + 16) * HSTR + b_loff) * 2);
            bq[0][2][0] = r0; bq[0][2][1] = r1;
            bq[0][3][0] = r2; bq[0][3][1] = r3;
        }

        #pragma unroll
        for (int ks = 0; ks < 4; ks++) {
            const int kk = ks * 16;
            const int cur = ks & 1, nxt = cur ^ 1;
            if (ks < 3) {
                const int kn = kk + 16;
                uint32_t r0, r1, r2, r3;
                ldsm4(r0, r1, r2, r3,
                      bBase + ((wc * 32) * HSTR + kn + b_loff) * 2);
                bq[nxt][0][0] = r0; bq[nxt][0][1] = r1;
                bq[nxt][1][0] = r2; bq[nxt][1][1] = r3;
                ldsm4(r0, r1, r2, r3,
                      bBase + ((wc * 32 + 16) * HSTR + kn + b_loff) * 2);
                bq[nxt][2][0] = r0; bq[nxt][2][1] = r1;
                bq[nxt][3][0] = r2; bq[nxt][3][1] = r3;
            }
            uint32_t a[4][4];
            #pragma unroll
            for (int mt = 0; mt < 4; mt++)
                ldsm4(a[mt][0], a[mt][1], a[mt][2], a[mt][3],
                      aBase + (((wr * 64 + mt * 16) * HSTR + kk) + a_loff) * 2);
            #pragma unroll
            for (int mt = 0; mt < 4; mt++)
                #pragma unroll
                for (int nt = 0; nt < 4; nt++)
                    HMMA(acc[mt][nt], a[mt], bq[cur][nt]);
        }
    }

    // epilogue: hoisted bias
    float bb[4][2];
    #pragma unroll
    for (int nt = 0; nt < 4; nt++) {
        int c = col0 + wc * 32 + nt * 8 + 2 * lc;
        bb[nt][0] = __ldg(&bias[c]);
        bb[nt][1] = __ldg(&bias[c + 1]);
    }
    #pragma unroll
    for (int mt = 0; mt < 4; mt++) {
        int r = row0 + wr * 64 + mt * 16 + lr;
        #pragma unroll
        for (int nt = 0; nt < 4; nt++) {
            int c = col0 + wc * 32 + nt * 8 + 2 * lc;
            float v00 = acc[mt][nt][0] + bb[nt][0], v01 = acc[mt][nt][1] + bb[nt][1];
            float v10 = acc[mt][nt][2] + bb[nt][0], v11 = acc[mt][nt][3] + bb[nt][1];
            if (half_out) {
                __half* C = (__half*)Cm;
                *reinterpret_cast<__half2*>(&C[(size_t)r * Nn + c]) =
                    __floats2half2_rn(v00, v01);
                *reinterpret_cast<__half2*>(&C[(size_t)(r + 8) * Nn + c]) =
                    __floats2half2_rn(v10, v11);
            } else {
                float* C = (float*)Cm;
                *reinterpret_cast<float2*>(&C[(size_t)r * Nn + c]) =
                    make_float2(v00, v01);
                *reinterpret_cast<float2*>(&C[(size_t)(r + 8) * Nn + c]) =
                    make_float2(v10, v11);
            }
        }
    }
}

// ---------------------------------------------------------------------------
// Flash attention (causal), fp16 m16n8k16 (R12 version).
// log2-domain softmax (Q pre-scaled by 0.125*log2 e), exp via packexp2.
// LPT CTA order; Q frags hoisted; row-sum via HMMA ones-B; 3-stage KV ring.
// ---------------------------------------------------------------------------
#define OFF_Q   0
#define KV_STG  (2 * 64 * HSTR)
#define OFF_KV  (128 * HSTR)
#define FA_SMEM_HALFS (OFF_KV + 3 * KV_STG)
#define FA_SMEM_BYTES (FA_SMEM_HALFS * 2)

__global__ __launch_bounds__(256, 2) void flash_h(
    const __half* __restrict__ qkv, __half* __restrict__ y)
{
    extern __shared__ __half smf[];
    __half* Qs = smf + OFF_Q;

    const int tid  = threadIdx.x;
    const int lane = tid & 31;
    const int w    = tid >> 5;
    const int lr   = lane >> 2;
    const int lc   = lane & 3;
    const int qt   = gridDim.x - 1 - blockIdx.x;   // LPT: heavy CTAs first
    const int h    = blockIdx.y;
    const int b    = blockIdx.z;
    const int q0   = qt * 128;

    const uint32_t smbase = smem_u32(smf);
    const uint32_t qBase  = smbase;

    const int lmr = lane & 7, lmj = lane >> 3;
    const int a_loff = ((lmj & 1) * 8 + lmr) * HSTR + (lmj >> 1) * 8;
    const int b_loff = ((lmj >> 1) * 8 + lmr) * HSTR + (lmj & 1) * 8;

    const size_t baseKV = (size_t)(b * TT) * C3 + h * DH;

    int kvr[2], kvd[2];
    #pragma unroll
    for (int i = 0; i < 2; i++) {
        int f = tid + i * 256;
        kvr[i] = f >> 3;
        kvd[i] = (f & 7) << 3;
    }
    auto issue_kv = [&](int st, int k0) {
        uint32_t kb = smbase + (OFF_KV + st * KV_STG) * 2;
        uint32_t vb = kb + 64 * HSTR * 2;
        #pragma unroll
        for (int i = 0; i < 2; i++) {
            cpasync16(kb + kvr[i] * 144 + kvd[i] * 2,
                      &qkv[baseKV + (size_t)(k0 + kvr[i]) * C3 + CC + kvd[i]]);
            cpasync16(vb + kvr[i] * 144 + kvd[i] * 2,
                      &qkv[baseKV + (size_t)(k0 + kvr[i]) * C3 + 2 * CC + kvd[i]]);
        }
        asm volatile("cp.async.commit_group;");
    };

    // Q tile [128 x 64] * (0.125 * log2 e)
    const __half2 qscale = __float2half2_rn(0.125f * 1.4426950408889634f);
    const size_t baseQ = (size_t)(b * TT + q0) * C3 + h * DH;
    #pragma unroll
    for (int i = 0; i < 4; i++) {
        int f  = tid + i * 256;
        int r  = f >> 3;
        int d8 = (f & 7) << 3;
        uint4 v = *reinterpret_cast<const uint4*>(&qkv[baseQ + (size_t)r * C3 + d8]);
        __half2* hv = reinterpret_cast<__half2*>(&v);
        hv[0] = __hmul2(hv[0], qscale);
        hv[1] = __hmul2(hv[1], qscale);
        hv[2] = __hmul2(hv[2], qscale);
        hv[3] = __hmul2(hv[3], qscale);
        *reinterpret_cast<uint4*>(&Qs[r * HSTR + d8]) = v;
    }

    const int nkt = 2 * qt + 2;
    issue_kv(0, 0);
    issue_kv(1, 64);

    __syncthreads();

    uint32_t qf[4][4];
    #pragma unroll
    for (int ks = 0; ks < 4; ks++)
        ldsm4(qf[ks][0], qf[ks][1], qf[ks][2], qf[ks][3],
              qBase + ((w * 16) * HSTR + ks * 16 + a_loff) * 2);

    float o[8][4];
    #pragma unroll
    for (int t = 0; t < 8; t++)
        #pragma unroll
        for (int j = 0; j < 4; j++) o[t][j] = 0.0f;
    float m0 = -1e30f, m1 = -1e30f, l0 = 0.0f, l1 = 0.0f;

    const int rmin = q0 + w * 16;
    const uint32_t onesb[2] = {0x3C003C00u, 0x3C003C00u};

    for (int kt = 0; kt < nkt; kt++) {
        if (kt + 1 < nkt) asm volatile("cp.async.wait_group 1;");
        else              asm volatile("cp.async.wait_group 0;");
        __syncthreads();

        if (kt + 2 < nkt) issue_kv((kt + 2) % 3, (kt + 2) * 64);

        const int k0 = kt * 64;
        if (k0 <= rmin + 15) {
            const uint32_t kBase = smbase + (OFF_KV + (kt % 3) * KV_STG) * 2;
            const __half* Vs = smf + OFF_KV + (kt % 3) * KV_STG + 64 * HSTR;

            float s[8][4];
            #pragma unroll
            for (int t = 0; t < 8; t++)
                #pragma unroll
                for (int j = 0; j < 4; j++) s[t][j] = 0.0f;

            #pragma unroll
            for (int ks = 0; ks < 4; ks++) {
                const int kk = ks * 16;
                #pragma unroll
                for (int p = 0; p < 4; p++) {
                    uint32_t r0, r1, r2, r3;
                    ldsm4(r0, r1, r2, r3,
                          kBase + ((p * 16) * HSTR + kk + b_loff) * 2);
                    uint32_t bf0[2] = {r0, r1};
                    uint32_t bf1[2] = {r2, r3};
                    HMMA(s[2 * p],     qf[ks], bf0);
                    HMMA(s[2 * p + 1], qf[ks], bf1);
                }
            }

            if (k0 + 63 > rmin) {
                #pragma unroll
                for (int t = 0; t < 8; t++) {
                    int c = k0 + t * 8 + 2 * lc;
                    if (c > rmin + lr)          s[t][0] = -1e30f;
                    if (c + 1 > rmin + lr)      s[t][1] = -1e30f;
                    if (c > rmin + lr + 8)      s[t][2] = -1e30f;
                    if (c + 1 > rmin + lr + 8)  s[t][3] = -1e30f;
                }
            }

            float mx0 = -1e30f, mx1 = -1e30f;
            #pragma unroll
            for (int t = 0; t < 8; t++) {
                mx0 = fmaxf(mx0, fmaxf(s[t][0], s[t][1]));
                mx1 = fmaxf(mx1, fmaxf(s[t][2], s[t][3]));
            }
            mx0 = fmaxf(mx0, __shfl_xor_sync(0xffffffffu, mx0, 1));
            mx0 = fmaxf(mx0, __shfl_xor_sync(0xffffffffu, mx0, 2));
            mx1 = fmaxf(mx1, __shfl_xor_sync(0xffffffffu, mx1, 1));
            mx1 = fmaxf(mx1, __shfl_xor_sync(0xffffffffu, mx1, 2));

            float mn0 = fmaxf(m0, mx0), mn1 = fmaxf(m1, mx1);
            float c0 = exp2f(m0 - mn0), c1 = exp2f(m1 - mn1);
            m0 = mn0; m1 = mn1;

            uint32_t pf[4][4];
            #pragma unroll
            for (int ks = 0; ks < 4; ks++) {
                pf[ks][0] = packexp2(s[2 * ks][0] - m0, s[2 * ks][1] - m0);
                pf[ks][1] = packexp2(s[2 * ks][2] - m1, s[2 * ks][3] - m1);
                pf[ks][2] = packexp2(s[2 * ks + 1][0] - m0, s[2 * ks + 1][1] - m0);
                pf[ks][3] = packexp2(s[2 * ks + 1][2] - m1, s[2 * ks + 1][3] - m1);
            }

            float lsum[4] = {0.0f, 0.0f, 0.0f, 0.0f};
            #pragma unroll
            for (int ks = 0; ks < 4; ks++)
                HMMA(lsum, pf[ks], onesb);
            l0 = l0 * c0 + lsum[0];
            l1 = l1 * c1 + lsum[2];

            #pragma unroll
            for (int t = 0; t < 8; t++) {
                o[t][0] *= c0; o[t][1] *= c0;
                o[t][2] *= c1; o[t][3] *= c1;
            }

            #pragma unroll
            for (int ks = 0; ks < 4; ks++) {
                const int kk = ks * 16;
                #pragma unroll
                for (int g = 0; g < 4; g++) {
                    int n0 = g * 16;
                    uint32_t vaddr = smem_u32(
                        &Vs[(kk + (lane & 15)) * HSTR + n0 + ((lane >> 4) << 3)]);
                    uint32_t r0, r1, r2, r3;
                    ldsm4t(r0, r1, r2, r3, vaddr);
                    uint32_t bf0[2] = {r0, r1};
                    uint32_t bf1[2] = {r2, r3};
                    HMMA(o[2 * g],     pf[ks], bf0);
                    HMMA(o[2 * g + 1], pf[ks], bf1);
                }
            }
        }
    }

    float inv0 = 1.0f / l0, inv1 = 1.0f / l1;
    const size_t baseY = (size_t)(b * TT + q0 + w * 16) * CC + h * DH;
    #pragma unroll
    for (int t = 0; t < 8; t++) {
        int c = t * 8 + 2 * lc;
        *reinterpret_cast<__half2*>(&y[baseY + (size_t)lr * CC + c]) =
            __floats2half2_rn(o[t][0] * inv0, o[t][1] * inv0);
        *reinterpret_cast<__half2*>(&y[baseY + (size_t)(lr + 8) * CC + c]) =
            __floats2half2_rn(o[t][2] * inv1, o[t][3] * inv1);
    }
}

// ---------------------------------------------------------------------------
extern "C" void kernel_launch(void* const* d_in, const int* in_sizes, int n_in,
                              void* d_out, int out_size)
{
    const float* x      = (const float*)d_in[0];
    const float* W_attn = (const float*)d_in[1];
    const float* b_attn = (const float*)d_in[2];
    const float* W_proj = (const float*)d_in[3];
    const float* b_proj = (const float*)d_in[4];
    float* out = (float*)d_out;

    __half *qkv_ptr, *y_ptr, *xh_ptr, *wat_ptr, *wpt_ptr;
    cudaGetSymbolAddress((void**)&qkv_ptr, g_qkv);
    cudaGetSymbolAddress((void**)&y_ptr, g_y);
    cudaGetSymbolAddress((void**)&xh_ptr, g_xh);
    cudaGetSymbolAddress((void**)&wat_ptr, g_wat);
    cudaGetSymbolAddress((void**)&wpt_ptr, g_wpt);

    static bool attr_set = false;
    if (!attr_set) {
        cudaFuncSetAttribute(flash_h,
                             cudaFuncAttributeMaxDynamicSharedMemorySize,
                             FA_SMEM_BYTES);
        cudaFuncSetAttribute(hgemm,
                             cudaFuncAttributeMaxDynamicSharedMemorySize,
                             HGEMM_SMEM_BYTES);
        attr_set = true;
    }

    // prep (single launch): fp16 x + transposed fp16 weights
    prep_all<<<dim3(C3 / 32, CC / 32, 3), dim3(32, 8)>>>(
        x, xh_ptr, W_attn, wat_ptr, W_proj, wpt_ptr);

    hgemm<<<dim3(C3 / 128, MROWS / 128), 256, HGEMM_SMEM_BYTES>>>(
        xh_ptr, wat_ptr, b_attn, qkv_ptr, MROWS, C3, CC, 1);

    flash_h<<<dim3(TT / 128, HH, BB), 256, FA_SMEM_BYTES>>>(qkv_ptr, y_ptr);

    hgemm<<<dim3(CC / 128, MROWS / 128), 256, HGEMM_SMEM_BYTES>>>(
        y_ptr, wpt_ptr, b_proj, out, MROWS, CC, CC, 0);
}

// round 16
// speedup vs baseline: 1.0093x; 1.0093x over previous
#include <cuda_runtime.h>
#include <cuda_fp16.h>
#include <math.h>
#include <stdint.h>

#define BB 4
#define TT 2048
#define CC 1024
#define HH 16
#define DH 64
#define MROWS (BB*TT)
#define C3   (3*CC)

// scratch (no cudaMalloc allowed)
__device__ __half g_qkv[(size_t)MROWS * C3];   // [M, 3C] fp16
__device__ __half g_y[(size_t)MROWS * CC];     // [M, C]  fp16
__device__ __half g_xh[(size_t)MROWS * CC];    // x fp16 [M, C]
__device__ __half g_wat[(size_t)C3 * CC];      // W_attn^T fp16 [3C, C]
__device__ __half g_wpt[(size_t)CC * CC];      // W_proj^T fp16 [C, C]

__device__ __forceinline__ uint32_t smem_u32(const void* p) {
    return (uint32_t)__cvta_generic_to_shared(p);
}
__device__ __forceinline__ void cpasync16(uint32_t dst_smem, const void* src) {
    asm volatile("cp.async.cg.shared.global [%0], [%1], 16;"
                 :: "r"(dst_smem), "l"(src));
}
__device__ __forceinline__ void ldsm4(uint32_t& r0, uint32_t& r1,
                                      uint32_t& r2, uint32_t& r3, uint32_t addr) {
    asm volatile("ldmatrix.sync.aligned.m8n8.x4.shared.b16 {%0,%1,%2,%3}, [%4];"
                 : "=r"(r0), "=r"(r1), "=r"(r2), "=r"(r3) : "r"(addr));
}
__device__ __forceinline__ void ldsm4t(uint32_t& r0, uint32_t& r1,
                                       uint32_t& r2, uint32_t& r3, uint32_t addr) {
    asm volatile("ldmatrix.sync.aligned.m8n8.x4.trans.shared.b16 {%0,%1,%2,%3}, [%4];"
                 : "=r"(r0), "=r"(r1), "=r"(r2), "=r"(r3) : "r"(addr));
}
#define HMMA(d, a, b)                                                        \
    asm volatile(                                                            \
        "mma.sync.aligned.m16n8k16.row.col.f32.f16.f16.f32 "                 \
        "{%0,%1,%2,%3}, {%4,%5,%6,%7}, {%8,%9}, {%0,%1,%2,%3};"              \
        : "+f"(d[0]), "+f"(d[1]), "+f"(d[2]), "+f"(d[3])                     \
        : "r"(a[0]), "r"(a[1]), "r"(a[2]), "r"(a[3]), "r"(b[0]), "r"(b[1]))

__device__ __forceinline__ uint32_t packexp2(float x, float y) {
    __half2 h = h2exp2(__floats2half2_rn(x, y));
    return *reinterpret_cast<uint32_t*>(&h);
}

// ====================== merged prep kernel (grid.z = 3) ====================
// z=0: fp32->fp16 round of x   z=1: W_attn transpose   z=2: W_proj transpose
__global__ void prep_all(const float* __restrict__ x, __half* __restrict__ xh,
                         const float* __restrict__ Wa, __half* __restrict__ Wat,
                         const float* __restrict__ Wp, __half* __restrict__ Wpt) {
    const int z = blockIdx.z;
    const int tx = threadIdx.x, ty = threadIdx.y;
    const int tid = ty * 32 + tx;
    if (z == 0) {
        const int n4 = MROWS * CC / 4;
        const int nth = gridDim.x * gridDim.y * 256;
        int base = (blockIdx.y * gridDim.x + blockIdx.x) * 256 + tid;
        for (int i = base; i < n4; i += nth) {
            float4 v = reinterpret_cast<const float4*>(x)[i];
            __half2* d = reinterpret_cast<__half2*>(xh) + 2 * i;
            d[0] = __floats2half2_rn(v.x, v.y);
            d[1] = __floats2half2_rn(v.z, v.w);
        }
        return;
    }
    __shared__ float t[32][33];
    const int Nn = (z == 1) ? C3 : CC;
    if (z == 2 && blockIdx.x >= CC / 32) return;
    const float* W = (z == 1) ? Wa : Wp;
    __half* Wt = (z == 1) ? Wat : Wpt;
    int n0 = blockIdx.x * 32, k0 = blockIdx.y * 32;
    #pragma unroll
    for (int j = 0; j < 4; j++)
        t[ty + j * 8][tx] = W[(size_t)(k0 + ty + j * 8) * Nn + n0 + tx];
    __syncthreads();
    #pragma unroll
    for (int j = 0; j < 4; j++)
        Wt[(size_t)(n0 + ty + j * 8) * CC + k0 + tx] =
            __float2half(t[tx][ty + j * 8]);
}

// ---------------------------------------------------------------------------
// FP16 GEMM (R12 loop): C[M,N] = A[M,K] @ Bt[N,K]^T + bias[N]
// block 256 (8 warps 2x4), tile 128x128, BK=64, 3-stage cp.async ring.
// ---------------------------------------------------------------------------
#define HSTR 72
#define HA_HALFS (128 * HSTR)
#define HSTAGE_BYTES (2 * HA_HALFS * 2)
#define HGEMM_SMEM_BYTES (3 * HSTAGE_BYTES)

__global__ __launch_bounds__(256, 2) void hgemm(
    const __half* __restrict__ A, const __half* __restrict__ Bt,
    const float* __restrict__ bias, void* __restrict__ Cm,
    int Mn, int Nn, int Kn, int half_out)
{
    extern __shared__ __half smh[];

    const int tid  = threadIdx.x;
    const int lane = tid & 31;
    const int warp = tid >> 5;
    const int wr   = warp & 1;
    const int wc   = warp >> 1;
    const int row0 = blockIdx.y * 128;
    const int col0 = blockIdx.x * 128;
    const int lr = lane >> 2;
    const int lc = lane & 3;

    const uint32_t smbase = smem_u32(smh);

    const int lmr = lane & 7, lmj = lane >> 3;
    const int a_loff = ((lmj & 1) * 8 + lmr) * HSTR + (lmj >> 1) * 8;
    const int b_loff = ((lmj >> 1) * 8 + lmr) * HSTR + (lmj & 1) * 8;

    int rr[4], k8[4];
    #pragma unroll
    for (int i = 0; i < 4; i++) {
        int f = tid + i * 256;
        rr[i] = f >> 3;
        k8[i] = (f & 7) << 3;
    }

    auto issue_stage = [&](int st, int k0) {
        uint32_t abase = smbase + st * HSTAGE_BYTES;
        uint32_t bbase = abase + HA_HALFS * 2;
        #pragma unroll
        for (int i = 0; i < 4; i++)
            cpasync16(abase + rr[i] * 144 + k8[i] * 2,
                      &A[(size_t)(row0 + rr[i]) * Kn + k0 + k8[i]]);
        #pragma unroll
        for (int i = 0; i < 4; i++)
            cpasync16(bbase + rr[i] * 144 + k8[i] * 2,
                      &Bt[(size_t)(col0 + rr[i]) * Kn + k0 + k8[i]]);
        asm volatile("cp.async.commit_group;");
    };

    float acc[4][4][4];
    #pragma unroll
    for (int i = 0; i < 4; i++)
        #pragma unroll
        for (int j = 0; j < 4; j++)
            #pragma unroll
            for (int k = 0; k < 4; k++) acc[i][j][k] = 0.0f;

    const int niter = Kn / 64;
    issue_stage(0, 0);
    if (niter > 1) issue_stage(1, 64);

    for (int it = 0; it < niter; it++) {
        if (it + 1 < niter) asm volatile("cp.async.wait_group 1;");
        else                asm volatile("cp.async.wait_group 0;");
        __syncthreads();

        if (it + 2 < niter) issue_stage((it + 2) % 3, (it + 2) * 64);

        const int stage = it % 3;
        const uint32_t aBase = smbase + stage * HSTAGE_BYTES;
        const uint32_t bBase = aBase + HA_HALFS * 2;

        #pragma unroll
        for (int ks = 0; ks < 4; ks++) {
            const int kk = ks * 16;
            uint32_t a[4][4], b[4][2];
            #pragma unroll
            for (int mt = 0; mt < 4; mt++)
                ldsm4(a[mt][0], a[mt][1], a[mt][2], a[mt][3],
                      aBase + (((wr * 64 + mt * 16) * HSTR + kk) + a_loff) * 2);
            #pragma unroll
            for (int p = 0; p < 2; p++) {
                uint32_t r0, r1, r2, r3;
                ldsm4(r0, r1, r2, r3,
                      bBase + (((wc * 32 + p * 16) * HSTR + kk) + b_loff) * 2);
                b[2 * p][0] = r0; b[2 * p][1] = r1;
                b[2 * p + 1][0] = r2; b[2 * p + 1][1] = r3;
            }
            #pragma unroll
            for (int mt = 0; mt < 4; mt++)
                #pragma unroll
                for (int nt = 0; nt < 4; nt++)
                    HMMA(acc[mt][nt], a[mt], b[nt]);
        }
    }

    // epilogue: bias hoisted out of the mt loop
    float bb[4][2];
    #pragma unroll
    for (int nt = 0; nt < 4; nt++) {
        int c = col0 + wc * 32 + nt * 8 + 2 * lc;
        bb[nt][0] = __ldg(&bias[c]);
        bb[nt][1] = __ldg(&bias[c + 1]);
    }
    #pragma unroll
    for (int mt = 0; mt < 4; mt++) {
        int r = row0 + wr * 64 + mt * 16 + lr;
        #pragma unroll
        for (int nt = 0; nt < 4; nt++) {
            int c = col0 + wc * 32 + nt * 8 + 2 * lc;
            float v00 = acc[mt][nt][0] + bb[nt][0], v01 = acc[mt][nt][1] + bb[nt][1];
            float v10 = acc[mt][nt][2] + bb[nt][0], v11 = acc[mt][nt][3] + bb[nt][1];
            if (half_out) {
                __half* C = (__half*)Cm;
                *reinterpret_cast<__half2*>(&C[(size_t)r * Nn + c]) =
                    __floats2half2_rn(v00, v01);
                *reinterpret_cast<__half2*>(&C[(size_t)(r + 8) * Nn + c]) =
                    __floats2half2_rn(v10, v11);
            } else {
                float* C = (float*)Cm;
                *reinterpret_cast<float2*>(&C[(size_t)r * Nn + c]) =
                    make_float2(v00, v01);
                *reinterpret_cast<float2*>(&C[(size_t)(r + 8) * Nn + c]) =
                    make_float2(v10, v11);
            }
        }
    }
}

// ---------------------------------------------------------------------------
// Flash attention (causal), fp16 m16n8k16 (R12 version; lsum split 2x2).
// log2-domain softmax (Q pre-scaled by 0.125*log2 e), exp via packexp2.
// LPT CTA order; Q frags hoisted; row-sum via HMMA ones-B; 3-stage KV ring.
// ---------------------------------------------------------------------------
#define OFF_Q   0
#define KV_STG  (2 * 64 * HSTR)
#define OFF_KV  (128 * HSTR)
#define FA_SMEM_HALFS (OFF_KV + 3 * KV_STG)
#define FA_SMEM_BYTES (FA_SMEM_HALFS * 2)

__global__ __launch_bounds__(256, 2) void flash_h(
    const __half* __restrict__ qkv, __half* __restrict__ y)
{
    extern __shared__ __half smf[];
    __half* Qs = smf + OFF_Q;

    const int tid  = threadIdx.x;
    const int lane = tid & 31;
    const int w    = tid >> 5;
    const int lr   = lane >> 2;
    const int lc   = lane & 3;
    const int qt   = gridDim.x - 1 - blockIdx.x;   // LPT: heavy CTAs first
    const int h    = blockIdx.y;
    const int b    = blockIdx.z;
    const int q0   = qt * 128;

    const uint32_t smbase = smem_u32(smf);
    const uint32_t qBase  = smbase;

    const int lmr = lane & 7, lmj = lane >> 3;
    const int a_loff = ((lmj & 1) * 8 + lmr) * HSTR + (lmj >> 1) * 8;
    const int b_loff = ((lmj >> 1) * 8 + lmr) * HSTR + (lmj & 1) * 8;

    const size_t baseKV = (size_t)(b * TT) * C3 + h * DH;

    int kvr[2], kvd[2];
    #pragma unroll
    for (int i = 0; i < 2; i++) {
        int f = tid + i * 256;
        kvr[i] = f >> 3;
        kvd[i] = (f & 7) << 3;
    }
    auto issue_kv = [&](int st, int k0) {
        uint32_t kb = smbase + (OFF_KV + st * KV_STG) * 2;
        uint32_t vb = kb + 64 * HSTR * 2;
        #pragma unroll
        for (int i = 0; i < 2; i++) {
            cpasync16(kb + kvr[i] * 144 + kvd[i] * 2,
                      &qkv[baseKV + (size_t)(k0 + kvr[i]) * C3 + CC + kvd[i]]);
            cpasync16(vb + kvr[i] * 144 + kvd[i] * 2,
                      &qkv[baseKV + (size_t)(k0 + kvr[i]) * C3 + 2 * CC + kvd[i]]);
        }
        asm volatile("cp.async.commit_group;");
    };

    // Q tile [128 x 64] * (0.125 * log2 e)
    const __half2 qscale = __float2half2_rn(0.125f * 1.4426950408889634f);
    const size_t baseQ = (size_t)(b * TT + q0) * C3 + h * DH;
    #pragma unroll
    for (int i = 0; i < 4; i++) {
        int f  = tid + i * 256;
        int r  = f >> 3;
        int d8 = (f & 7) << 3;
        uint4 v = *reinterpret_cast<const uint4*>(&qkv[baseQ + (size_t)r * C3 + d8]);
        __half2* hv = reinterpret_cast<__half2*>(&v);
        hv[0] = __hmul2(hv[0], qscale);
        hv[1] = __hmul2(hv[1], qscale);
        hv[2] = __hmul2(hv[2], qscale);
        hv[3] = __hmul2(hv[3], qscale);
        *reinterpret_cast<uint4*>(&Qs[r * HSTR + d8]) = v;
    }

    const int nkt = 2 * qt + 2;
    issue_kv(0, 0);
    issue_kv(1, 64);

    __syncthreads();

    uint32_t qf[4][4];
    #pragma unroll
    for (int ks = 0; ks < 4; ks++)
        ldsm4(qf[ks][0], qf[ks][1], qf[ks][2], qf[ks][3],
              qBase + ((w * 16) * HSTR + ks * 16 + a_loff) * 2);

    float o[8][4];
    #pragma unroll
    for (int t = 0; t < 8; t++)
        #pragma unroll
        for (int j = 0; j < 4; j++) o[t][j] = 0.0f;
    float m0 = -1e30f, m1 = -1e30f, l0 = 0.0f, l1 = 0.0f;

    const int rmin = q0 + w * 16;
    const uint32_t onesb[2] = {0x3C003C00u, 0x3C003C00u};

    for (int kt = 0; kt < nkt; kt++) {
        if (kt + 1 < nkt) asm volatile("cp.async.wait_group 1;");
        else              asm volatile("cp.async.wait_group 0;");
        __syncthreads();

        if (kt + 2 < nkt) issue_kv((kt + 2) % 3, (kt + 2) * 64);

        const int k0 = kt * 64;
        if (k0 <= rmin + 15) {
            const uint32_t kBase = smbase + (OFF_KV + (kt % 3) * KV_STG) * 2;
            const __half* Vs = smf + OFF_KV + (kt % 3) * KV_STG + 64 * HSTR;

            float s[8][4];
            #pragma unroll
            for (int t = 0; t < 8; t++)
                #pragma unroll
                for (int j = 0; j < 4; j++) s[t][j] = 0.0f;

            #pragma unroll
            for (int ks = 0; ks < 4; ks++) {
                const int kk = ks * 16;
                #pragma unroll
                for (int p = 0; p < 4; p++) {
                    uint32_t r0, r1, r2, r3;
                    ldsm4(r0, r1, r2, r3,
                          kBase + ((p * 16) * HSTR + kk + b_loff) * 2);
                    uint32_t bf0[2] = {r0, r1};
                    uint32_t bf1[2] = {r2, r3};
                    HMMA(s[2 * p],     qf[ks], bf0);
                    HMMA(s[2 * p + 1], qf[ks], bf1);
                }
            }

            if (k0 + 63 > rmin) {
                #pragma unroll
                for (int t = 0; t < 8; t++) {
                    int c = k0 + t * 8 + 2 * lc;
                    if (c > rmin + lr)          s[t][0] = -1e30f;
                    if (c + 1 > rmin + lr)      s[t][1] = -1e30f;
                    if (c > rmin + lr + 8)      s[t][2] = -1e30f;
                    if (c + 1 > rmin + lr + 8)  s[t][3] = -1e30f;
                }
            }

            float mx0 = -1e30f, mx1 = -1e30f;
            #pragma unroll
            for (int t = 0; t < 8; t++) {
                mx0 = fmaxf(mx0, fmaxf(s[t][0], s[t][1]));
                mx1 = fmaxf(mx1, fmaxf(s[t][2], s[t][3]));
            }
            mx0 = fmaxf(mx0, __shfl_xor_sync(0xffffffffu, mx0, 1));
            mx0 = fmaxf(mx0, __shfl_xor_sync(0xffffffffu, mx0, 2));
            mx1 = fmaxf(mx1, __shfl_xor_sync(0xffffffffu, mx1, 1));
            mx1 = fmaxf(mx1, __shfl_xor_sync(0xffffffffu, mx1, 2));

            float mn0 = fmaxf(m0, mx0), mn1 = fmaxf(m1, mx1);
            float c0 = exp2f(m0 - mn0), c1 = exp2f(m1 - mn1);
            m0 = mn0; m1 = mn1;

            uint32_t pf[4][4];
            #pragma unroll
            for (int ks = 0; ks < 4; ks++) {
                pf[ks][0] = packexp2(s[2 * ks][0] - m0, s[2 * ks][1] - m0);
                pf[ks][1] = packexp2(s[2 * ks][2] - m1, s[2 * ks][3] - m1);
                pf[ks][2] = packexp2(s[2 * ks + 1][0] - m0, s[2 * ks + 1][1] - m0);
                pf[ks][3] = packexp2(s[2 * ks + 1][2] - m1, s[2 * ks + 1][3] - m1);
            }

            // row sums via HMMA ones-B; two independent chains to shorten
            // the serial tensor dependency
            float lsA[4] = {0.0f, 0.0f, 0.0f, 0.0f};
            float lsB[4] = {0.0f, 0.0f, 0.0f, 0.0f};
            HMMA(lsA, pf[0], onesb);
            HMMA(lsB, pf[1], onesb);
            HMMA(lsA, pf[2], onesb);
            HMMA(lsB, pf[3], onesb);
            l0 = l0 * c0 + (lsA[0] + lsB[0]);
            l1 = l1 * c1 + (lsA[2] + lsB[2]);

            #pragma unroll
            for (int t = 0; t < 8; t++) {
                o[t][0] *= c0; o[t][1] *= c0;
                o[t][2] *= c1; o[t][3] *= c1;
            }

            #pragma unroll
            for (int ks = 0; ks < 4; ks++) {
                const int kk = ks * 16;
                #pragma unroll
                for (int g = 0; g < 4; g++) {
                    int n0 = g * 16;
                    uint32_t vaddr = smem_u32(
                        &Vs[(kk + (lane & 15)) * HSTR + n0 + ((lane >> 4) << 3)]);
                    uint32_t r0, r1, r2, r3;
                    ldsm4t(r0, r1, r2, r3, vaddr);
                    uint32_t bf0[2] = {r0, r1};
                    uint32_t bf1[2] = {r2, r3};
                    HMMA(o[2 * g],     pf[ks], bf0);
                    HMMA(o[2 * g + 1], pf[ks], bf1);
                }
            }
        }
    }

    float inv0 = 1.0f / l0, inv1 = 1.0f / l1;
    const size_t baseY = (size_t)(b * TT + q0 + w * 16) * CC + h * DH;
    #pragma unroll
    for (int t = 0; t < 8; t++) {
        int c = t * 8 + 2 * lc;
        *reinterpret_cast<__half2*>(&y[baseY + (size_t)lr * CC + c]) =
            __floats2half2_rn(o[t][0] * inv0, o[t][1] * inv0);
        *reinterpret_cast<__half2*>(&y[baseY + (size_t)(lr + 8) * CC + c]) =
            __floats2half2_rn(o[t][2] * inv1, o[t][3] * inv1);
    }
}

// ---------------------------------------------------------------------------
extern "C" void kernel_launch(void* const* d_in, const int* in_sizes, int n_in,
                              void* d_out, int out_size)
{
    const float* x      = (const float*)d_in[0];
    const float* W_attn = (const float*)d_in[1];
    const float* b_attn = (const float*)d_in[2];
    const float* W_proj = (const float*)d_in[3];
    const float* b_proj = (const float*)d_in[4];
    float* out = (float*)d_out;

    __half *qkv_ptr, *y_ptr, *xh_ptr, *wat_ptr, *wpt_ptr;
    cudaGetSymbolAddress((void**)&qkv_ptr, g_qkv);
    cudaGetSymbolAddress((void**)&y_ptr, g_y);
    cudaGetSymbolAddress((void**)&xh_ptr, g_xh);
    cudaGetSymbolAddress((void**)&wat_ptr, g_wat);
    cudaGetSymbolAddress((void**)&wpt_ptr, g_wpt);

    static bool attr_set = false;
    if (!attr_set) {
        cudaFuncSetAttribute(flash_h,
                             cudaFuncAttributeMaxDynamicSharedMemorySize,
                             FA_SMEM_BYTES);
        cudaFuncSetAttribute(hgemm,
                             cudaFuncAttributeMaxDynamicSharedMemorySize,
                             HGEMM_SMEM_BYTES);
        attr_set = true;
    }

    // prep (single launch): fp16 x + transposed fp16 weights
    prep_all<<<dim3(C3 / 32, CC / 32, 3), dim3(32, 8)>>>(
        x, xh_ptr, W_attn, wat_ptr, W_proj, wpt_ptr);

    hgemm<<<dim3(C3 / 128, MROWS / 128), 256, HGEMM_SMEM_BYTES>>>(
        xh_ptr, wat_ptr, b_attn, qkv_ptr, MROWS, C3, CC, 1);

    flash_h<<<dim3(TT / 128, HH, BB), 256, FA_SMEM_BYTES>>>(qkv_ptr, y_ptr);

    hgemm<<<dim3(CC / 128, MROWS / 128), 256, HGEMM_SMEM_BYTES>>>(
        y_ptr, wpt_ptr, b_proj, out, MROWS, CC, CC, 0);
}

// round 17
// speedup vs baseline: 1.0129x; 1.0036x over previous
#include <cuda_runtime.h>
#include <cuda_fp16.h>
#include <math.h>
#include <stdint.h>

#define BB 4
#define TT 2048
#define CC 1024
#define HH 16
#define DH 64
#define MROWS (BB*TT)
#define C3   (3*CC)

// scratch (no cudaMalloc allowed)
__device__ __half g_qkv[(size_t)MROWS * C3];   // [M, 3C] fp16
__device__ __half g_y[(size_t)MROWS * CC];     // [M, C]  fp16
__device__ __half g_xh[(size_t)MROWS * CC];    // x fp16 [M, C]
__device__ __half g_wat[(size_t)C3 * CC];      // W_attn^T fp16 [3C, C]
__device__ __half g_wpt[(size_t)CC * CC];      // W_proj^T fp16 [C, C]

__device__ __forceinline__ uint32_t smem_u32(const void* p) {
    return (uint32_t)__cvta_generic_to_shared(p);
}
__device__ __forceinline__ void cpasync16(uint32_t dst_smem, const void* src) {
    asm volatile("cp.async.cg.shared.global [%0], [%1], 16;"
                 :: "r"(dst_smem), "l"(src));
}
__device__ __forceinline__ void ldsm4(uint32_t& r0, uint32_t& r1,
                                      uint32_t& r2, uint32_t& r3, uint32_t addr) {
    asm volatile("ldmatrix.sync.aligned.m8n8.x4.shared.b16 {%0,%1,%2,%3}, [%4];"
                 : "=r"(r0), "=r"(r1), "=r"(r2), "=r"(r3) : "r"(addr));
}
__device__ __forceinline__ void ldsm4t(uint32_t& r0, uint32_t& r1,
                                       uint32_t& r2, uint32_t& r3, uint32_t addr) {
    asm volatile("ldmatrix.sync.aligned.m8n8.x4.trans.shared.b16 {%0,%1,%2,%3}, [%4];"
                 : "=r"(r0), "=r"(r1), "=r"(r2), "=r"(r3) : "r"(addr));
}
#define HMMA(d, a, b)                                                        \
    asm volatile(                                                            \
        "mma.sync.aligned.m16n8k16.row.col.f32.f16.f16.f32 "                 \
        "{%0,%1,%2,%3}, {%4,%5,%6,%7}, {%8,%9}, {%0,%1,%2,%3};"              \
        : "+f"(d[0]), "+f"(d[1]), "+f"(d[2]), "+f"(d[3])                     \
        : "r"(a[0]), "r"(a[1]), "r"(a[2]), "r"(a[3]), "r"(b[0]), "r"(b[1]))

__device__ __forceinline__ uint32_t packexp2(float x, float y) {
    __half2 h = h2exp2(__floats2half2_rn(x, y));
    return *reinterpret_cast<uint32_t*>(&h);
}

// ====================== merged prep kernel (grid.z = 3) ====================
__global__ void prep_all(const float* __restrict__ x, __half* __restrict__ xh,
                         const float* __restrict__ Wa, __half* __restrict__ Wat,
                         const float* __restrict__ Wp, __half* __restrict__ Wpt) {
    const int z = blockIdx.z;
    const int tx = threadIdx.x, ty = threadIdx.y;
    const int tid = ty * 32 + tx;
    if (z == 0) {
        const int n4 = MROWS * CC / 4;
        const int nth = gridDim.x * gridDim.y * 256;
        int base = (blockIdx.y * gridDim.x + blockIdx.x) * 256 + tid;
        for (int i = base; i < n4; i += nth) {
            float4 v = reinterpret_cast<const float4*>(x)[i];
            __half2* d = reinterpret_cast<__half2*>(xh) + 2 * i;
            d[0] = __floats2half2_rn(v.x, v.y);
            d[1] = __floats2half2_rn(v.z, v.w);
        }
        return;
    }
    __shared__ float t[32][33];
    const int Nn = (z == 1) ? C3 : CC;
    if (z == 2 && blockIdx.x >= CC / 32) return;
    const float* W = (z == 1) ? Wa : Wp;
    __half* Wt = (z == 1) ? Wat : Wpt;
    int n0 = blockIdx.x * 32, k0 = blockIdx.y * 32;
    #pragma unroll
    for (int j = 0; j < 4; j++)
        t[ty + j * 8][tx] = W[(size_t)(k0 + ty + j * 8) * Nn + n0 + tx];
    __syncthreads();
    #pragma unroll
    for (int j = 0; j < 4; j++)
        Wt[(size_t)(n0 + ty + j * 8) * CC + k0 + tx] =
            __float2half(t[tx][ty + j * 8]);
}

// ---------------------------------------------------------------------------
// FP16 GEMM (R16): C[M,N] = A[M,K] @ Bt[N,K]^T + bias[N]
// ---------------------------------------------------------------------------
#define HSTR 72
#define HA_HALFS (128 * HSTR)
#define HSTAGE_BYTES (2 * HA_HALFS * 2)
#define HGEMM_SMEM_BYTES (3 * HSTAGE_BYTES)

__global__ __launch_bounds__(256, 2) void hgemm(
    const __half* __restrict__ A, const __half* __restrict__ Bt,
    const float* __restrict__ bias, void* __restrict__ Cm,
    int Mn, int Nn, int Kn, int half_out)
{
    extern __shared__ __half smh[];

    const int tid  = threadIdx.x;
    const int lane = tid & 31;
    const int warp = tid >> 5;
    const int wr   = warp & 1;
    const int wc   = warp >> 1;
    const int row0 = blockIdx.y * 128;
    const int col0 = blockIdx.x * 128;
    const int lr = lane >> 2;
    const int lc = lane & 3;

    const uint32_t smbase = smem_u32(smh);

    const int lmr = lane & 7, lmj = lane >> 3;
    const int a_loff = ((lmj & 1) * 8 + lmr) * HSTR + (lmj >> 1) * 8;
    const int b_loff = ((lmj >> 1) * 8 + lmr) * HSTR + (lmj & 1) * 8;

    int rr[4], k8[4];
    #pragma unroll
    for (int i = 0; i < 4; i++) {
        int f = tid + i * 256;
        rr[i] = f >> 3;
        k8[i] = (f & 7) << 3;
    }

    auto issue_stage = [&](int st, int k0) {
        uint32_t abase = smbase + st * HSTAGE_BYTES;
        uint32_t bbase = abase + HA_HALFS * 2;
        #pragma unroll
        for (int i = 0; i < 4; i++)
            cpasync16(abase + rr[i] * 144 + k8[i] * 2,
                      &A[(size_t)(row0 + rr[i]) * Kn + k0 + k8[i]]);
        #pragma unroll
        for (int i = 0; i < 4; i++)
            cpasync16(bbase + rr[i] * 144 + k8[i] * 2,
                      &Bt[(size_t)(col0 + rr[i]) * Kn + k0 + k8[i]]);
        asm volatile("cp.async.commit_group;");
    };

    float acc[4][4][4];
    #pragma unroll
    for (int i = 0; i < 4; i++)
        #pragma unroll
        for (int j = 0; j < 4; j++)
            #pragma unroll
            for (int k = 0; k < 4; k++) acc[i][j][k] = 0.0f;

    const int niter = Kn / 64;
    issue_stage(0, 0);
    if (niter > 1) issue_stage(1, 64);

    for (int it = 0; it < niter; it++) {
        if (it + 1 < niter) asm volatile("cp.async.wait_group 1;");
        else                asm volatile("cp.async.wait_group 0;");
        __syncthreads();

        if (it + 2 < niter) issue_stage((it + 2) % 3, (it + 2) * 64);

        const int stage = it % 3;
        const uint32_t aBase = smbase + stage * HSTAGE_BYTES;
        const uint32_t bBase = aBase + HA_HALFS * 2;

        #pragma unroll
        for (int ks = 0; ks < 4; ks++) {
            const int kk = ks * 16;
            uint32_t a[4][4], b[4][2];
            #pragma unroll
            for (int mt = 0; mt < 4; mt++)
                ldsm4(a[mt][0], a[mt][1], a[mt][2], a[mt][3],
                      aBase + (((wr * 64 + mt * 16) * HSTR + kk) + a_loff) * 2);
            #pragma unroll
            for (int p = 0; p < 2; p++) {
                uint32_t r0, r1, r2, r3;
                ldsm4(r0, r1, r2, r3,
                      bBase + (((wc * 32 + p * 16) * HSTR + kk) + b_loff) * 2);
                b[2 * p][0] = r0; b[2 * p][1] = r1;
                b[2 * p + 1][0] = r2; b[2 * p + 1][1] = r3;
            }
            #pragma unroll
            for (int mt = 0; mt < 4; mt++)
                #pragma unroll
                for (int nt = 0; nt < 4; nt++)
                    HMMA(acc[mt][nt], a[mt], b[nt]);
        }
    }

    float bb[4][2];
    #pragma unroll
    for (int nt = 0; nt < 4; nt++) {
        int c = col0 + wc * 32 + nt * 8 + 2 * lc;
        bb[nt][0] = __ldg(&bias[c]);
        bb[nt][1] = __ldg(&bias[c + 1]);
    }
    #pragma unroll
    for (int mt = 0; mt < 4; mt++) {
        int r = row0 + wr * 64 + mt * 16 + lr;
        #pragma unroll
        for (int nt = 0; nt < 4; nt++) {
            int c = col0 + wc * 32 + nt * 8 + 2 * lc;
            float v00 = acc[mt][nt][0] + bb[nt][0], v01 = acc[mt][nt][1] + bb[nt][1];
            float v10 = acc[mt][nt][2] + bb[nt][0], v11 = acc[mt][nt][3] + bb[nt][1];
            if (half_out) {
                __half* C = (__half*)Cm;
                *reinterpret_cast<__half2*>(&C[(size_t)r * Nn + c]) =
                    __floats2half2_rn(v00, v01);
                *reinterpret_cast<__half2*>(&C[(size_t)(r + 8) * Nn + c]) =
                    __floats2half2_rn(v10, v11);
            } else {
                float* C = (float*)Cm;
                *reinterpret_cast<float2*>(&C[(size_t)r * Nn + c]) =
                    make_float2(v00, v01);
                *reinterpret_cast<float2*>(&C[(size_t)(r + 8) * Nn + c]) =
                    make_float2(v10, v11);
            }
        }
    }
}

// ---------------------------------------------------------------------------
// Flash attention (causal), fp16 m16n8k16.
// R16 + V-fragment prefetch (ks=0, g=0..1) issued before the softmax chain.
// ---------------------------------------------------------------------------
#define OFF_Q   0
#define KV_STG  (2 * 64 * HSTR)
#define OFF_KV  (128 * HSTR)
#define FA_SMEM_HALFS (OFF_KV + 3 * KV_STG)
#define FA_SMEM_BYTES (FA_SMEM_HALFS * 2)

__global__ __launch_bounds__(256, 2) void flash_h(
    const __half* __restrict__ qkv, __half* __restrict__ y)
{
    extern __shared__ __half smf[];
    __half* Qs = smf + OFF_Q;

    const int tid  = threadIdx.x;
    const int lane = tid & 31;
    const int w    = tid >> 5;
    const int lr   = lane >> 2;
    const int lc   = lane & 3;
    const int qt   = gridDim.x - 1 - blockIdx.x;   // LPT: heavy CTAs first
    const int h    = blockIdx.y;
    const int b    = blockIdx.z;
    const int q0   = qt * 128;

    const uint32_t smbase = smem_u32(smf);
    const uint32_t qBase  = smbase;

    const int lmr = lane & 7, lmj = lane >> 3;
    const int a_loff = ((lmj & 1) * 8 + lmr) * HSTR + (lmj >> 1) * 8;
    const int b_loff = ((lmj >> 1) * 8 + lmr) * HSTR + (lmj & 1) * 8;

    const size_t baseKV = (size_t)(b * TT) * C3 + h * DH;

    int kvr[2], kvd[2];
    #pragma unroll
    for (int i = 0; i < 2; i++) {
        int f = tid + i * 256;
        kvr[i] = f >> 3;
        kvd[i] = (f & 7) << 3;
    }
    auto issue_kv = [&](int st, int k0) {
        uint32_t kb = smbase + (OFF_KV + st * KV_STG) * 2;
        uint32_t vb = kb + 64 * HSTR * 2;
        #pragma unroll
        for (int i = 0; i < 2; i++) {
            cpasync16(kb + kvr[i] * 144 + kvd[i] * 2,
                      &qkv[baseKV + (size_t)(k0 + kvr[i]) * C3 + CC + kvd[i]]);
            cpasync16(vb + kvr[i] * 144 + kvd[i] * 2,
                      &qkv[baseKV + (size_t)(k0 + kvr[i]) * C3 + 2 * CC + kvd[i]]);
        }
        asm volatile("cp.async.commit_group;");
    };

    const __half2 qscale = __float2half2_rn(0.125f * 1.4426950408889634f);
    const size_t baseQ = (size_t)(b * TT + q0) * C3 + h * DH;
    #pragma unroll
    for (int i = 0; i < 4; i++) {
        int f  = tid + i * 256;
        int r  = f >> 3;
        int d8 = (f & 7) << 3;
        uint4 v = *reinterpret_cast<const uint4*>(&qkv[baseQ + (size_t)r * C3 + d8]);
        __half2* hv = reinterpret_cast<__half2*>(&v);
        hv[0] = __hmul2(hv[0], qscale);
        hv[1] = __hmul2(hv[1], qscale);
        hv[2] = __hmul2(hv[2], qscale);
        hv[3] = __hmul2(hv[3], qscale);
        *reinterpret_cast<uint4*>(&Qs[r * HSTR + d8]) = v;
    }

    const int nkt = 2 * qt + 2;
    issue_kv(0, 0);
    issue_kv(1, 64);

    __syncthreads();

    uint32_t qf[4][4];
    #pragma unroll
    for (int ks = 0; ks < 4; ks++)
        ldsm4(qf[ks][0], qf[ks][1], qf[ks][2], qf[ks][3],
              qBase + ((w * 16) * HSTR + ks * 16 + a_loff) * 2);

    float o[8][4];
    #pragma unroll
    for (int t = 0; t < 8; t++)
        #pragma unroll
        for (int j = 0; j < 4; j++) o[t][j] = 0.0f;
    float m0 = -1e30f, m1 = -1e30f, l0 = 0.0f, l1 = 0.0f;

    const int rmin = q0 + w * 16;
    const uint32_t onesb[2] = {0x3C003C00u, 0x3C003C00u};

    for (int kt = 0; kt < nkt; kt++) {
        if (kt + 1 < nkt) asm volatile("cp.async.wait_group 1;");
        else              asm volatile("cp.async.wait_group 0;");
        __syncthreads();

        if (kt + 2 < nkt) issue_kv((kt + 2) % 3, (kt + 2) * 64);

        const int k0 = kt * 64;
        if (k0 <= rmin + 15) {
            const uint32_t kBase = smbase + (OFF_KV + (kt % 3) * KV_STG) * 2;
            const __half* Vs = smf + OFF_KV + (kt % 3) * KV_STG + 64 * HSTR;

            float s[8][4];
            #pragma unroll
            for (int t = 0; t < 8; t++)
                #pragma unroll
                for (int j = 0; j < 4; j++) s[t][j] = 0.0f;

            #pragma unroll
            for (int ks = 0; ks < 4; ks++) {
                const int kk = ks * 16;
                #pragma unroll
                for (int p = 0; p < 4; p++) {
                    uint32_t r0, r1, r2, r3;
                    ldsm4(r0, r1, r2, r3,
                          kBase + ((p * 16) * HSTR + kk + b_loff) * 2);
                    uint32_t bf0[2] = {r0, r1};
                    uint32_t bf1[2] = {r2, r3};
                    HMMA(s[2 * p],     qf[ks], bf0);
                    HMMA(s[2 * p + 1], qf[ks], bf1);
                }
            }

            if (k0 + 63 > rmin) {
                #pragma unroll
                for (int t = 0; t < 8; t++) {
                    int c = k0 + t * 8 + 2 * lc;
                    if (c > rmin + lr)          s[t][0] = -1e30f;
                    if (c + 1 > rmin + lr)      s[t][1] = -1e30f;
                    if (c > rmin + lr + 8)      s[t][2] = -1e30f;
                    if (c + 1 > rmin + lr + 8)  s[t][3] = -1e30f;
                }
            }

            // prefetch first two V fragments (ks=0, g=0..1) so the LDS
            // latency hides under the shuffle chain below (8 regs)
            uint32_t vpre[2][4];
            #pragma unroll
            for (int g = 0; g < 2; g++) {
                uint32_t vaddr = smem_u32(
                    &Vs[(lane & 15) * HSTR + g * 16 + ((lane >> 4) << 3)]);
                ldsm4t(vpre[g][0], vpre[g][1], vpre[g][2], vpre[g][3], vaddr);
            }

            float mx0 = -1e30f, mx1 = -1e30f;
            #pragma unroll
            for (int t = 0; t < 8; t++) {
                mx0 = fmaxf(mx0, fmaxf(s[t][0], s[t][1]));
                mx1 = fmaxf(mx1, fmaxf(s[t][2], s[t][3]));
            }
            mx0 = fmaxf(mx0, __shfl_xor_sync(0xffffffffu, mx0, 1));
            mx0 = fmaxf(mx0, __shfl_xor_sync(0xffffffffu, mx0, 2));
            mx1 = fmaxf(mx1, __shfl_xor_sync(0xffffffffu, mx1, 1));
            mx1 = fmaxf(mx1, __shfl_xor_sync(0xffffffffu, mx1, 2));

            float mn0 = fmaxf(m0, mx0), mn1 = fmaxf(m1, mx1);
            float c0 = exp2f(m0 - mn0), c1 = exp2f(m1 - mn1);
            m0 = mn0; m1 = mn1;

            uint32_t pf[4][4];
            #pragma unroll
            for (int ks = 0; ks < 4; ks++) {
                pf[ks][0] = packexp2(s[2 * ks][0] - m0, s[2 * ks][1] - m0);
                pf[ks][1] = packexp2(s[2 * ks][2] - m1, s[2 * ks][3] - m1);
                pf[ks][2] = packexp2(s[2 * ks + 1][0] - m0, s[2 * ks + 1][1] - m0);
                pf[ks][3] = packexp2(s[2 * ks + 1][2] - m1, s[2 * ks + 1][3] - m1);
            }

            float lsA[4] = {0.0f, 0.0f, 0.0f, 0.0f};
            float lsB[4] = {0.0f, 0.0f, 0.0f, 0.0f};
            HMMA(lsA, pf[0], onesb);
            HMMA(lsB, pf[1], onesb);
            HMMA(lsA, pf[2], onesb);
            HMMA(lsB, pf[3], onesb);
            l0 = l0 * c0 + (lsA[0] + lsB[0]);
            l1 = l1 * c1 + (lsA[2] + lsB[2]);

            #pragma unroll
            for (int t = 0; t < 8; t++) {
                o[t][0] *= c0; o[t][1] *= c0;
                o[t][2] *= c1; o[t][3] *= c1;
            }

            // ---- O += P @ V (ks=0/g=0..1 use prefetched fragments) ----
            #pragma unroll
            for (int ks = 0; ks < 4; ks++) {
                const int kk = ks * 16;
                #pragma unroll
                for (int g = 0; g < 4; g++) {
                    uint32_t r0, r1, r2, r3;
                    if (ks == 0 && g < 2) {
                        r0 = vpre[g][0]; r1 = vpre[g][1];
                        r2 = vpre[g][2]; r3 = vpre[g][3];
                    } else {
                        uint32_t vaddr = smem_u32(
                            &Vs[(kk + (lane & 15)) * HSTR + g * 16 +
                                ((lane >> 4) << 3)]);
                        ldsm4t(r0, r1, r2, r3, vaddr);
                    }
                    uint32_t bf0[2] = {r0, r1};
                    uint32_t bf1[2] = {r2, r3};
                    HMMA(o[2 * g],     pf[ks], bf0);
                    HMMA(o[2 * g + 1], pf[ks], bf1);
                }
            }
        }
    }

    float inv0 = 1.0f / l0, inv1 = 1.0f / l1;
    const size_t baseY = (size_t)(b * TT + q0 + w * 16) * CC + h * DH;
    #pragma unroll
    for (int t = 0; t < 8; t++) {
        int c = t * 8 + 2 * lc;
        *reinterpret_cast<__half2*>(&y[baseY + (size_t)lr * CC + c]) =
            __floats2half2_rn(o[t][0] * inv0, o[t][1] * inv0);
        *reinterpret_cast<__half2*>(&y[baseY + (size_t)(lr + 8) * CC + c]) =
            __floats2half2_rn(o[t][2] * inv1, o[t][3] * inv1);
    }
}

// ---------------------------------------------------------------------------
extern "C" void kernel_launch(void* const* d_in, const int* in_sizes, int n_in,
                              void* d_out, int out_size)
{
    const float* x      = (const float*)d_in[0];
    const float* W_attn = (const float*)d_in[1];
    const float* b_attn = (const float*)d_in[2];
    const float* W_proj = (const float*)d_in[3];
    const float* b_proj = (const float*)d_in[4];
    float* out = (float*)d_out;

    __half *qkv_ptr, *y_ptr, *xh_ptr, *wat_ptr, *wpt_ptr;
    cudaGetSymbolAddress((void**)&qkv_ptr, g_qkv);
    cudaGetSymbolAddress((void**)&y_ptr, g_y);
    cudaGetSymbolAddress((void**)&xh_ptr, g_xh);
    cudaGetSymbolAddress((void**)&wat_ptr, g_wat);
    cudaGetSymbolAddress((void**)&wpt_ptr, g_wpt);

    static bool attr_set = false;
    if (!attr_set) {
        cudaFuncSetAttribute(flash_h,
                             cudaFuncAttributeMaxDynamicSharedMemorySize,
                             FA_SMEM_BYTES);
        cudaFuncSetAttribute(hgemm,
                             cudaFuncAttributeMaxDynamicSharedMemorySize,
                             HGEMM_SMEM_BYTES);
        attr_set = true;
    }

    prep_all<<<dim3(C3 / 32, CC / 32, 3), dim3(32, 8)>>>(
        x, xh_ptr, W_attn, wat_ptr, W_proj, wpt_ptr);

    hgemm<<<dim3(C3 / 128, MROWS / 128), 256, HGEMM_SMEM_BYTES>>>(
        xh_ptr, wat_ptr, b_attn, qkv_ptr, MROWS, C3, CC, 1);

    flash_h<<<dim3(TT / 128, HH, BB), 256, FA_SMEM_BYTES>>>(qkv_ptr, y_ptr);

    hgemm<<<dim3(CC / 128, MROWS / 128), 256, HGEMM_SMEM_BYTES>>>(
        y_ptr, wpt_ptr, b_proj, out, MROWS, CC, CC, 0);
}